// round 2
// baseline (speedup 1.0000x reference)
#include <cuda_runtime.h>

// out[b, i*512+j] = 9 * sum_{t=0..8} w[i,j,t]*mask_i(i,t)*diag[b, j+t] + sum_t b[i,j,t]
// diag[b,j] = inputs[b,j,j,0]; diag treated as 0 for j >= 512 (valid_j mask).
// mask_i(i,t) = (i + t/3 < 512).

#define SDIM 512
#define DPAD 524          // 512 + 8 needed, padded to multiple of 4 for float4 alignment
#define MAXB 128

__device__ float g_diag[MAXB * DPAD];

__global__ void extract_diag_kernel(const float* __restrict__ in) {
    const int b = blockIdx.x;
    const int j = threadIdx.x;                       // 0..511
    // inputs[b, j, j, 0] -> linear b*512*512 + j*513
    g_diag[b * DPAD + j] = in[(size_t)b * (SDIM * SDIM) + (size_t)j * (SDIM + 1)];
    if (j < DPAD - SDIM)                             // zero tail padding (valid_j mask)
        g_diag[b * DPAD + SDIM + j] = 0.0f;
}

__global__ void __launch_bounds__(128) parse_cnn_main_kernel(
    const float* __restrict__ w, const float* __restrict__ bb,
    float* __restrict__ out, int B, int bchunk)
{
    const int i   = blockIdx.x;                      // output row, 0..511
    const int tid = threadIdx.x;                     // 0..127
    const int j0  = tid * 4;                         // 4 consecutive j per thread

    // per-t-group row-validity mask (t/3 in {0,1,2})
    float m[3];
    m[0] = 1.0f;
    m[1] = (i + 1 < SDIM) ? 1.0f : 0.0f;
    m[2] = (i + 2 < SDIM) ? 1.0f : 0.0f;

    // Preload masked weights (x9 folded in) and bias sums for our 4 columns.
    float wt[4][9];
    float bias[4];
    const size_t base = (size_t)(i * SDIM + j0) * 9;
    #pragma unroll
    for (int jj = 0; jj < 4; ++jj) {
        float bs = 0.0f;
        #pragma unroll
        for (int t = 0; t < 9; ++t) {
            wt[jj][t] = 9.0f * w[base + jj * 9 + t] * m[t / 3];
            bs += bb[base + jj * 9 + t];
        }
        bias[jj] = bs;
    }

    const int b0 = blockIdx.y * bchunk;
    int b1 = b0 + bchunk; if (b1 > B) b1 = B;

    for (int b = b0; b < b1; ++b) {
        // 12 diag values cover j0..j0+11 (4 outputs x 9 taps, overlapping)
        const float4* dp = (const float4*)(g_diag + b * DPAD + j0);
        float4 v0 = dp[0], v1 = dp[1], v2 = dp[2];
        float d[12] = { v0.x, v0.y, v0.z, v0.w,
                        v1.x, v1.y, v1.z, v1.w,
                        v2.x, v2.y, v2.z, v2.w };

        float acc[4];
        #pragma unroll
        for (int jj = 0; jj < 4; ++jj) {
            float s = bias[jj];
            #pragma unroll
            for (int t = 0; t < 9; ++t)
                s += wt[jj][t] * d[jj + t];
            acc[jj] = s;
        }

        float4 o; o.x = acc[0]; o.y = acc[1]; o.z = acc[2]; o.w = acc[3];
        *((float4*)(out + (size_t)b * (SDIM * SDIM) + i * SDIM + j0)) = o;
    }
}

extern "C" void kernel_launch(void* const* d_in, const int* in_sizes, int n_in,
                              void* d_out, int out_size) {
    const float* in = (const float*)d_in[0];   // inputs (B,512,512,1) f32
    const float* w  = (const float*)d_in[1];   // w (512*512*9,) f32
    const float* bb = (const float*)d_in[2];   // b (512*512*9,) f32
    float* out = (float*)d_out;                // (B, 512*512) f32

    const int B = in_sizes[0] / (SDIM * SDIM); // 100

    extract_diag_kernel<<<B, SDIM>>>(in);

    const int nby = 4;                         // batch chunks for occupancy
    const int bchunk = (B + nby - 1) / nby;
    dim3 grid(SDIM, nby);
    parse_cnn_main_kernel<<<grid, 128>>>(w, bb, out, B, bchunk);
}